// round 12
// baseline (speedup 1.0000x reference)
#include <cuda_runtime.h>
#include <cstdint>

// Shapes (fixed): b=4096, d=1024, u=32, r=32, n_obs=25
#define B_DIM 4096
#define D_DIM 1024
#define U_DIM 32
#define OBS_DIM 25

// ---------------------------------------------------------------------------
// Device scratch (all GEMM operands pre-rounded to tf32)
// ---------------------------------------------------------------------------
__device__ float g_ut_dt[B_DIM * U_DIM];   // ut*dt, FULL fp32 (epilogue scales)
__device__ float g_utc[B_DIM * U_DIM];     // tf32-rounded ut*dt (GEMM operand)
__device__ float g_Zc[B_DIM * D_DIM];      // tf32-rounded z_dyn
__device__ float g_Ac[D_DIM * D_DIM];      // tf32-rounded A_bilinear       [N,K]
__device__ float g_Bc[D_DIM * U_DIM];      // tf32-rounded B_bilinear       [N,K]
__device__ float g_WqT[D_DIM * D_DIM];     // tf32  WqT[(m*32+r)][j] = N_Q[m,j,r]
__device__ float g_WpT[D_DIM * D_DIM];     // tf32  WpT[i][(m*32+r)] = N_P[m,i,r]
__device__ float g_S[B_DIM * D_DIM];       // tf32-rounded S[b, m*32+r]

// ---------------------------------------------------------------------------
// Helpers
// ---------------------------------------------------------------------------
__device__ __forceinline__ uint32_t f2tf32(float x) {
    uint32_t r;
    asm("cvt.rna.tf32.f32 %0, %1;" : "=r"(r) : "f"(x));
    return r;
}
__device__ __forceinline__ float tf32v(float x) { return __uint_as_float(f2tf32(x)); }
__device__ __forceinline__ uint32_t smem_u32(const void* p) {
    uint32_t a;
    asm("{ .reg .u64 t; cvta.to.shared.u64 t, %1; cvt.u32.u64 %0, t; }" : "=r"(a) : "l"(p));
    return a;
}
__device__ __forceinline__ void mma_tf32(float (&c)[4], const uint32_t (&a)[4],
                                         const uint32_t (&b)[2]) {
    asm volatile(
        "mma.sync.aligned.m16n8k8.row.col.f32.tf32.tf32.f32 "
        "{%0,%1,%2,%3}, {%4,%5,%6,%7}, {%8,%9}, {%0,%1,%2,%3};"
        : "+f"(c[0]), "+f"(c[1]), "+f"(c[2]), "+f"(c[3])
        : "r"(a[0]), "r"(a[1]), "r"(a[2]), "r"(a[3]), "r"(b[0]), "r"(b[1]));
}
__device__ __forceinline__ void ldsm4(uint32_t (&r)[4], uint32_t a) {
    asm volatile("ldmatrix.sync.aligned.m8n8.x4.shared.b16 {%0,%1,%2,%3}, [%4];"
                 : "=r"(r[0]), "=r"(r[1]), "=r"(r[2]), "=r"(r[3]) : "r"(a));
}
__device__ __forceinline__ void cp16(uint32_t dst, const void* src) {
    asm volatile("cp.async.cg.shared.global [%0], [%1], 16;" :: "r"(dst), "l"(src));
}
#define CP_COMMIT() asm volatile("cp.async.commit_group;" ::: "memory")
#define CP_WAIT1()  asm volatile("cp.async.wait_group 1;" ::: "memory")

// ---------------------------------------------------------------------------
// Prep kernels (tf32 rounding folded in)
// ---------------------------------------------------------------------------
__global__ void prep_ut_dt(const float* __restrict__ ut, const float* __restrict__ dt) {
    int idx = blockIdx.x * 256 + threadIdx.x;
    if (idx < B_DIM * U_DIM) {
        float v = ut[idx] * dt[0];
        g_ut_dt[idx] = v;
        g_utc[idx] = tf32v(v);
    }
}
__global__ void cvt_arr(const float* __restrict__ in, float* __restrict__ out, int n) {
    int idx = blockIdx.x * 256 + threadIdx.x;
    if (idx < n) out[idx] = tf32v(in[idx]);
}
__global__ void prep_wqT(const float* __restrict__ NQ) {
    __shared__ float t[32][33];
    int m = blockIdx.y;
    int j0 = blockIdx.x * 32;
    t[threadIdx.y][threadIdx.x] = NQ[m * 32768 + (j0 + threadIdx.y) * 32 + threadIdx.x];
    __syncthreads();
    g_WqT[(m * 32 + threadIdx.y) * D_DIM + j0 + threadIdx.x] = tf32v(t[threadIdx.x][threadIdx.y]);
}
__global__ void prep_wpT(const float* __restrict__ NP) {
    int idx = blockIdx.x * 256 + threadIdx.x;   // 1M
    int i = idx >> 10;
    int c = idx & 1023;
    int m = c >> 5;
    int r = c & 31;
    g_WpT[idx] = tf32v(NP[m * 32768 + i * 32 + r]);
}

// ---------------------------------------------------------------------------
// GEMM: CTA 128x128, BK=64, 512 threads = 16 warps (4m x 4n of 32x32 tiles).
// Smem row = 256B (64 floats), 16B-unit swizzle: unit u stored at u^(row&7).
// 3-stage cp.async pipeline: (A 32KB + B 32KB) x 3 = 192KB dynamic smem.
// Fragment double-buffering overlaps ldsm (MIO) with mma (tensor).
// ---------------------------------------------------------------------------
#define A_BYTES 32768
#define B_BYTES 32768
#define STAGE_BYTES (A_BYTES + B_BYTES)
#define SMEM_NEED (3 * STAGE_BYTES)
#define NTHREADS 512
#define ROWB 256

__device__ __forceinline__ void chunk_src_1(int c, int brow, int bcol,
                                            const float*& a, int& alda,
                                            const float*& b, int& bldb) {
    a = g_Zc + brow * D_DIM + c * 64;   alda = D_DIM;
    b = g_WqT + bcol * D_DIM + c * 64;  bldb = D_DIM;
}
__device__ __forceinline__ void chunk_src_2(int c, int brow, int bcol,
                                            const float*& a, int& alda,
                                            const float*& b, int& bldb) {
    if (c < 16)      { a = g_Zc + brow * D_DIM + c * 64;         alda = D_DIM;
                       b = g_Ac + bcol * D_DIM + c * 64;         bldb = D_DIM; }
    else if (c < 32) { a = g_S + brow * D_DIM + (c - 16) * 64;   alda = D_DIM;
                       b = g_WpT + bcol * D_DIM + (c - 16) * 64; bldb = D_DIM; }
    else             { a = g_utc + brow * U_DIM;                 alda = U_DIM;
                       b = g_Bc + bcol * U_DIM;                  bldb = U_DIM; }
}

// One stage: per thread 4 A-units + 4 B-units of 16B (u = q + 4i, u < kunits)
__device__ __forceinline__ void issue_stage(const float* __restrict__ a, int alda,
                                            const float* __restrict__ b, int bldb,
                                            uint32_t abase, uint32_t bbase, int kunits) {
    const int t = threadIdx.x;
    const int row = t >> 2, q = t & 3;
    const int sw = row & 7;
#pragma unroll
    for (int i = 0; i < 4; ++i) {
        int u = q + 4 * i;
        if (u < kunits) {
            cp16(abase + row * ROWB + ((u ^ sw) << 4), a + row * alda + u * 4);
            cp16(bbase + row * ROWB + ((u ^ sw) << 4), b + row * bldb + u * 4);
        }
    }
}

template <int KD8>
__device__ __forceinline__ void compute_chunk(uint32_t abase, uint32_t bbase,
                                              float (&acc)[2][4][4],
                                              int m0, int n0, int lane) {
    const int e3 = lane & 7;
    const int rA = e3 + ((lane >> 3) & 1) * 8;
    const int hA = lane >> 4;
    const int rB = e3 + ((lane >> 4) & 1) * 8;
    const int hB = (lane >> 3) & 1;

    uint32_t afr[2][2][4];   // [buf][mt][4]
    uint32_t bfr[2][4][2];   // [buf][nt][2]

    // load fragments for k8 = 0 into buf 0
    {
        const int c16b = 0;
#pragma unroll
        for (int mt = 0; mt < 2; ++mt)
            ldsm4(afr[0][mt], abase + (uint32_t)((m0 + mt * 16 + rA) * ROWB +
                                                 (((c16b + hA) ^ e3) << 4)));
#pragma unroll
        for (int p = 0; p < 2; ++p) {
            uint32_t tmp[4];
            ldsm4(tmp, bbase + (uint32_t)((n0 + p * 16 + rB) * ROWB +
                                          (((c16b + hB) ^ e3) << 4)));
            bfr[0][2 * p][0] = tmp[0]; bfr[0][2 * p][1] = tmp[1];
            bfr[0][2 * p + 1][0] = tmp[2]; bfr[0][2 * p + 1][1] = tmp[3];
        }
    }
#pragma unroll
    for (int kk = 0; kk < KD8; ++kk) {
        const int cur = kk & 1, nxt = cur ^ 1;
        if (kk + 1 < KD8) {   // prefetch next k8 fragments (overlaps with mmas)
            const int c16b = 2 * (kk + 1);
#pragma unroll
            for (int mt = 0; mt < 2; ++mt)
                ldsm4(afr[nxt][mt], abase + (uint32_t)((m0 + mt * 16 + rA) * ROWB +
                                                       (((c16b + hA) ^ e3) << 4)));
#pragma unroll
            for (int p = 0; p < 2; ++p) {
                uint32_t tmp[4];
                ldsm4(tmp, bbase + (uint32_t)((n0 + p * 16 + rB) * ROWB +
                                              (((c16b + hB) ^ e3) << 4)));
                bfr[nxt][2 * p][0] = tmp[0]; bfr[nxt][2 * p][1] = tmp[1];
                bfr[nxt][2 * p + 1][0] = tmp[2]; bfr[nxt][2 * p + 1][1] = tmp[3];
            }
        }
#pragma unroll
        for (int mt = 0; mt < 2; ++mt)
#pragma unroll
            for (int nt = 0; nt < 4; ++nt)
                mma_tf32(acc[mt][nt], afr[cur][mt], bfr[cur][nt]);
    }
}

template <int MODE>   // 1: GEMM1 (C=16 -> g_S scaled+rounded); 2: GEMM2 (C=33 -> out)
__global__ void __launch_bounds__(NTHREADS, 1) gemm_mma(float* __restrict__ outp)
{
    extern __shared__ char dsm[];
    const uint32_t sb = smem_u32(dsm);
    uint32_t aoff[3], boff[3];
#pragma unroll
    for (int s = 0; s < 3; ++s) {
        aoff[s] = sb + s * STAGE_BYTES;
        boff[s] = sb + s * STAGE_BYTES + A_BYTES;
    }

    const int t = threadIdx.x;
    const int lane = t & 31;
    const int w = t >> 5;
    const int m0 = (w >> 2) * 32;
    const int n0 = (w & 3) * 32;
    const int brow = blockIdx.y * 128;
    const int bcol = blockIdx.x * 128;
    const int C = (MODE == 1) ? 16 : 33;

    float acc[2][4][4];
#pragma unroll
    for (int mt = 0; mt < 2; ++mt)
#pragma unroll
        for (int nt = 0; nt < 4; ++nt)
#pragma unroll
            for (int i = 0; i < 4; ++i) acc[mt][nt][i] = 0.f;

    const float *a, *b;
    int alda, bldb;

    // prologue: stages 0,1 (both full-depth in both modes)
#pragma unroll
    for (int s = 0; s < 2; ++s) {
        if (MODE == 1) chunk_src_1(s, brow, bcol, a, alda, b, bldb);
        else           chunk_src_2(s, brow, bcol, a, alda, b, bldb);
        issue_stage(a, alda, b, bldb, aoff[s], boff[s], 16);
        CP_COMMIT();
    }

    int buf = 0;
    for (int c = 0; c < C; ++c) {
        CP_WAIT1();            // stage c complete
        __syncthreads();
        if (c + 2 < C) {       // stage c+2 into buffer (c+2)%3
            if (MODE == 1) chunk_src_1(c + 2, brow, bcol, a, alda, b, bldb);
            else           chunk_src_2(c + 2, brow, bcol, a, alda, b, bldb);
            int s = (c + 2) % 3;
            int ku = (MODE == 2 && c + 2 == 32) ? 8 : 16;
            issue_stage(a, alda, b, bldb, aoff[s], boff[s], ku);
        }
        CP_COMMIT();
        if (MODE == 2 && c == 32)
            compute_chunk<4>(aoff[buf], boff[buf], acc, m0, n0, lane);
        else
            compute_chunk<8>(aoff[buf], boff[buf], acc, m0, n0, lane);
        buf = (buf + 1) % 3;
    }

    // Epilogue (m16n8 C layout: lane -> rows {r, r+8}, col pair 2*(lane&3))
    const int r = lane >> 2;
    const int cp = (lane & 3) * 2;
#pragma unroll
    for (int mt = 0; mt < 2; ++mt) {
        const int row0 = brow + m0 + mt * 16 + r;
        const int row1 = row0 + 8;
#pragma unroll
        for (int nt = 0; nt < 4; ++nt) {
            const int colbase = bcol + n0 + nt * 8;
            const int col = colbase + cp;
            if (MODE == 1) {
                const int g = colbase >> 5;
                const float s0 = g_ut_dt[row0 * U_DIM + g];
                const float s1 = g_ut_dt[row1 * U_DIM + g];
                float2 v0 = { tf32v(acc[mt][nt][0] * s0), tf32v(acc[mt][nt][1] * s0) };
                float2 v1 = { tf32v(acc[mt][nt][2] * s1), tf32v(acc[mt][nt][3] * s1) };
                *(float2*)&g_S[row0 * D_DIM + col] = v0;
                *(float2*)&g_S[row1 * D_DIM + col] = v1;
            } else {
                float2 v0 = { acc[mt][nt][0], acc[mt][nt][1] };
                float2 v1 = { acc[mt][nt][2], acc[mt][nt][3] };
                *(float2*)&outp[row0 * D_DIM + col] = v0;
                *(float2*)&outp[row1 * D_DIM + col] = v1;
            }
        }
    }
}

// ---------------------------------------------------------------------------
// yt = Z @ C^T + ut_dt @ D^T  (exact fp32)
// ---------------------------------------------------------------------------
__global__ void __launch_bounds__(128) yt_kernel(const float* __restrict__ Z,
                                                 const float* __restrict__ C,
                                                 const float* __restrict__ Dm,
                                                 float* __restrict__ yt)
{
    __shared__ float Cs[OBS_DIM][132];
    const int lane = threadIdx.x & 31;
    const int warp = threadIdx.x >> 5;
    const int b = blockIdx.x * 4 + warp;

    float acc[OBS_DIM];
    {
        float ud = g_ut_dt[b * U_DIM + lane];
#pragma unroll
        for (int o = 0; o < OBS_DIM; ++o) acc[o] = ud * Dm[o * U_DIM + lane];
    }
    for (int kt = 0; kt < D_DIM; kt += 128) {
        __syncthreads();
        for (int idx = threadIdx.x; idx < OBS_DIM * 128; idx += 128) {
            int o = idx >> 7, kk = idx & 127;
            Cs[o][kk] = C[o * D_DIM + kt + kk];
        }
        __syncthreads();
        float4 zv = *(const float4*)(Z + b * D_DIM + kt + lane * 4);
#pragma unroll
        for (int o = 0; o < OBS_DIM; ++o) {
            float4 cv = *(const float4*)&Cs[o][lane * 4];
            acc[o] += zv.x * cv.x + zv.y * cv.y + zv.z * cv.z + zv.w * cv.w;
        }
    }
#pragma unroll
    for (int o = 0; o < OBS_DIM; ++o) {
#pragma unroll
        for (int off = 16; off; off >>= 1)
            acc[o] += __shfl_xor_sync(0xffffffffu, acc[o], off);
    }
    if (lane == 0) {
#pragma unroll
        for (int o = 0; o < OBS_DIM; ++o) yt[b * OBS_DIM + o] = acc[o];
    }
}

// ---------------------------------------------------------------------------
// Launch
// ---------------------------------------------------------------------------
extern "C" void kernel_launch(void* const* d_in, const int* in_sizes, int n_in,
                              void* d_out, int out_size) {
    const float* z_dyn = (const float*)d_in[0];
    // d_in[1] = z_static (unused)
    const float* dt = (const float*)d_in[2];
    const float* ut = (const float*)d_in[3];
    const float* A = (const float*)d_in[4];
    const float* Bb = (const float*)d_in[5];
    const float* NP = (const float*)d_in[6];
    const float* NQ = (const float*)d_in[7];
    const float* C = (const float*)d_in[8];
    const float* Dm = (const float*)d_in[9];
    float* out = (float*)d_out;

    cudaFuncSetAttribute(gemm_mma<1>, cudaFuncAttributeMaxDynamicSharedMemorySize, SMEM_NEED);
    cudaFuncSetAttribute(gemm_mma<2>, cudaFuncAttributeMaxDynamicSharedMemorySize, SMEM_NEED);

    float* zc; float* ac; float* bc;
    cudaGetSymbolAddress((void**)&zc, g_Zc);
    cudaGetSymbolAddress((void**)&ac, g_Ac);
    cudaGetSymbolAddress((void**)&bc, g_Bc);

    prep_ut_dt<<<(B_DIM * U_DIM + 255) / 256, 256>>>(ut, dt);
    cvt_arr<<<(B_DIM * D_DIM + 255) / 256, 256>>>(z_dyn, zc, B_DIM * D_DIM);
    cvt_arr<<<(D_DIM * D_DIM + 255) / 256, 256>>>(A, ac, D_DIM * D_DIM);
    cvt_arr<<<(D_DIM * U_DIM + 255) / 256, 256>>>(Bb, bc, D_DIM * U_DIM);
    prep_wqT<<<dim3(D_DIM / 32, U_DIM), dim3(32, 32)>>>(NQ);
    prep_wpT<<<(D_DIM * D_DIM) / 256, 256>>>(NP);

    dim3 grid(D_DIM / 128, B_DIM / 128);   // (8, 32) = 256 CTAs
    gemm_mma<1><<<grid, NTHREADS, SMEM_NEED>>>(out);
    gemm_mma<2><<<grid, NTHREADS, SMEM_NEED>>>(out);

    yt_kernel<<<B_DIM / 4, 128>>>(out, C, Dm, out + B_DIM * D_DIM);
}

// round 13
// speedup vs baseline: 1.1584x; 1.1584x over previous
#include <cuda_runtime.h>
#include <cstdint>

// Shapes (fixed): b=4096, d=1024, u=32, r=32, n_obs=25
#define B_DIM 4096
#define D_DIM 1024
#define U_DIM 32
#define OBS_DIM 25

// ---------------------------------------------------------------------------
// Device scratch (all GEMM operands pre-rounded to tf32)
// ---------------------------------------------------------------------------
__device__ float g_ut_dt[B_DIM * U_DIM];   // ut*dt, FULL fp32 (epilogue scales)
__device__ float g_utc[B_DIM * U_DIM];     // tf32-rounded ut*dt (GEMM operand)
__device__ float g_Zc[B_DIM * D_DIM];      // tf32-rounded z_dyn
__device__ float g_Ac[D_DIM * D_DIM];      // tf32-rounded A_bilinear       [N,K]
__device__ float g_Bc[D_DIM * U_DIM];      // tf32-rounded B_bilinear       [N,K]
__device__ float g_WqT[D_DIM * D_DIM];     // tf32  WqT[(m*32+r)][j] = N_Q[m,j,r]
__device__ float g_WpT[D_DIM * D_DIM];     // tf32  WpT[i][(m*32+r)] = N_P[m,i,r]
__device__ float g_S[B_DIM * D_DIM];       // tf32-rounded S[b, m*32+r]

// ---------------------------------------------------------------------------
// Helpers
// ---------------------------------------------------------------------------
__device__ __forceinline__ uint32_t f2tf32(float x) {
    uint32_t r;
    asm("cvt.rna.tf32.f32 %0, %1;" : "=r"(r) : "f"(x));
    return r;
}
__device__ __forceinline__ float tf32v(float x) { return __uint_as_float(f2tf32(x)); }
__device__ __forceinline__ uint32_t smem_u32(const void* p) {
    uint32_t a;
    asm("{ .reg .u64 t; cvta.to.shared.u64 t, %1; cvt.u32.u64 %0, t; }" : "=r"(a) : "l"(p));
    return a;
}
__device__ __forceinline__ void mma_tf32(float (&c)[4], const uint32_t (&a)[4],
                                         const uint32_t (&b)[2]) {
    asm volatile(
        "mma.sync.aligned.m16n8k8.row.col.f32.tf32.tf32.f32 "
        "{%0,%1,%2,%3}, {%4,%5,%6,%7}, {%8,%9}, {%0,%1,%2,%3};"
        : "+f"(c[0]), "+f"(c[1]), "+f"(c[2]), "+f"(c[3])
        : "r"(a[0]), "r"(a[1]), "r"(a[2]), "r"(a[3]), "r"(b[0]), "r"(b[1]));
}
__device__ __forceinline__ void ldsm4(uint32_t (&r)[4], uint32_t a) {
    asm volatile("ldmatrix.sync.aligned.m8n8.x4.shared.b16 {%0,%1,%2,%3}, [%4];"
                 : "=r"(r[0]), "=r"(r[1]), "=r"(r[2]), "=r"(r[3]) : "r"(a));
}
__device__ __forceinline__ void cp16(uint32_t dst, const void* src) {
    asm volatile("cp.async.cg.shared.global [%0], [%1], 16;" :: "r"(dst), "l"(src));
}
#define CP_COMMIT() asm volatile("cp.async.commit_group;" ::: "memory")
#define CP_WAIT1()  asm volatile("cp.async.wait_group 1;" ::: "memory")

// ---------------------------------------------------------------------------
// Prep: one fused grid-stride kernel (z, A, Wp, B, ut) + WqT smem transpose
// ---------------------------------------------------------------------------
__global__ void prep_fused(const float* __restrict__ z, const float* __restrict__ A,
                           const float* __restrict__ Bb, const float* __restrict__ NP,
                           const float* __restrict__ ut, const float* __restrict__ dt) {
    const int stride = gridDim.x * blockDim.x;
    const int tid = blockIdx.x * blockDim.x + threadIdx.x;
    const float dtv = dt[0];
    for (int i = tid; i < B_DIM * D_DIM; i += stride) g_Zc[i] = tf32v(z[i]);
    for (int i = tid; i < D_DIM * D_DIM; i += stride) g_Ac[i] = tf32v(A[i]);
    for (int i = tid; i < D_DIM * D_DIM; i += stride) {
        int ii = i >> 10, c = i & 1023, m = c >> 5, r = c & 31;
        g_WpT[i] = tf32v(NP[m * 32768 + ii * 32 + r]);   // warp reads 128B contiguous
    }
    for (int i = tid; i < D_DIM * U_DIM; i += stride) g_Bc[i] = tf32v(Bb[i]);
    for (int i = tid; i < B_DIM * U_DIM; i += stride) {
        float v = ut[i] * dtv;
        g_ut_dt[i] = v;
        g_utc[i] = tf32v(v);
    }
}
__global__ void prep_wqT(const float* __restrict__ NQ) {
    __shared__ float t[32][33];
    int m = blockIdx.y;
    int j0 = blockIdx.x * 32;
    t[threadIdx.y][threadIdx.x] = NQ[m * 32768 + (j0 + threadIdx.y) * 32 + threadIdx.x];
    __syncthreads();
    g_WqT[(m * 32 + threadIdx.y) * D_DIM + j0 + threadIdx.x] = tf32v(t[threadIdx.x][threadIdx.y]);
}

// ---------------------------------------------------------------------------
// GEMM (R11-best config): CTA 128x256, BK=32, 512 threads = 16 warps
// (4m x 4n of 32x64 tiles). Smem row = 128B, 16B-unit swizzle (c16 ^ (row&7)).
// 3-stage cp.async pipeline: (A 16KB + B 32KB) x 3 = 144KB dynamic smem.
// ---------------------------------------------------------------------------
#define A_BYTES 16384
#define B_BYTES 32768
#define STAGE_BYTES (A_BYTES + B_BYTES)
#define SMEM_NEED (3 * STAGE_BYTES)
#define NTHREADS 512

__device__ __forceinline__ void chunk_src_1(int c, int brow, int bcol,
                                            const float*& a, int& alda,
                                            const float*& b, int& bldb) {
    a = g_Zc + brow * D_DIM + c * 32;   alda = D_DIM;
    b = g_WqT + bcol * D_DIM + c * 32;  bldb = D_DIM;
}
__device__ __forceinline__ void chunk_src_2(int c, int brow, int bcol,
                                            const float*& a, int& alda,
                                            const float*& b, int& bldb) {
    if (c < 32)      { a = g_Zc + brow * D_DIM + c * 32;         alda = D_DIM;
                       b = g_Ac + bcol * D_DIM + c * 32;         bldb = D_DIM; }
    else if (c < 64) { a = g_S + brow * D_DIM + (c - 32) * 32;   alda = D_DIM;
                       b = g_WpT + bcol * D_DIM + (c - 32) * 32; bldb = D_DIM; }
    else             { a = g_utc + brow * U_DIM;                 alda = U_DIM;
                       b = g_Bc + bcol * U_DIM;                  bldb = U_DIM; }
}

// Issue cp.async for one stage: 6x16B per thread (A:2, B:4)
__device__ __forceinline__ void issue_stage(const float* __restrict__ a, int alda,
                                            const float* __restrict__ b, int bldb,
                                            uint32_t abase, uint32_t bbase) {
    const int t = threadIdx.x;
    {   // A: unit u = t, row 0..127, quarter q
        int row = t >> 2, q = t & 3;
        const float* p = a + row * alda + q * 8;
        uint32_t rp = abase + row * 128;
        cp16(rp + (((2 * q) ^ (row & 7)) << 4), p);
        cp16(rp + (((2 * q + 1) ^ (row & 7)) << 4), p + 4);
    }
#pragma unroll
    for (int i = 0; i < 2; ++i) {   // B: units t, t+512 -> rows 0..255
        int j = t + i * NTHREADS;
        int row = j >> 2, q = j & 3;
        const float* p = b + row * bldb + q * 8;
        uint32_t rp = bbase + row * 128;
        cp16(rp + (((2 * q) ^ (row & 7)) << 4), p);
        cp16(rp + (((2 * q + 1) ^ (row & 7)) << 4), p + 4);
    }
}

__device__ __forceinline__ void compute_chunk(uint32_t abase, uint32_t bbase,
                                              float (&acc)[2][8][4],
                                              int m0, int n0, int lane) {
    const int e3 = lane & 7;
    const int rA = e3 + ((lane >> 3) & 1) * 8;
    const int hA = lane >> 4;
    const int rB = e3 + ((lane >> 4) & 1) * 8;
    const int hB = (lane >> 3) & 1;
#pragma unroll
    for (int k8 = 0; k8 < 4; ++k8) {
        const int c16b = 2 * k8;
        uint32_t afr[2][4];
#pragma unroll
        for (int mt = 0; mt < 2; ++mt) {
            uint32_t addr = abase + (uint32_t)((m0 + mt * 16 + rA) * 128 +
                                               (((c16b + hA) ^ e3) << 4));
            ldsm4(afr[mt], addr);
        }
        uint32_t bfr[8][2];
#pragma unroll
        for (int p = 0; p < 4; ++p) {
            uint32_t tmp[4];
            uint32_t addr = bbase + (uint32_t)((n0 + p * 16 + rB) * 128 +
                                               (((c16b + hB) ^ e3) << 4));
            ldsm4(tmp, addr);
            bfr[2 * p][0] = tmp[0]; bfr[2 * p][1] = tmp[1];
            bfr[2 * p + 1][0] = tmp[2]; bfr[2 * p + 1][1] = tmp[3];
        }
#pragma unroll
        for (int mt = 0; mt < 2; ++mt)
#pragma unroll
            for (int nt = 0; nt < 8; ++nt)
                mma_tf32(acc[mt][nt], afr[mt], bfr[nt]);
    }
}

template <int MODE>   // 1: GEMM1 (C=32 -> g_S scaled+rounded); 2: GEMM2 (C=65 -> out)
__global__ void __launch_bounds__(NTHREADS, 1) gemm_mma(float* __restrict__ outp)
{
    extern __shared__ char dsm[];
    const uint32_t sb = smem_u32(dsm);
    uint32_t aoff[3], boff[3];
#pragma unroll
    for (int s = 0; s < 3; ++s) {
        aoff[s] = sb + s * STAGE_BYTES;
        boff[s] = sb + s * STAGE_BYTES + A_BYTES;
    }

    const int t = threadIdx.x;
    const int lane = t & 31;
    const int w = t >> 5;
    const int m0 = (w >> 2) * 32;
    const int n0 = (w & 3) * 64;
    const int brow = blockIdx.y * 128;
    const int bcol = blockIdx.x * 256;
    const int C = (MODE == 1) ? 32 : 65;

    float acc[2][8][4];
#pragma unroll
    for (int mt = 0; mt < 2; ++mt)
#pragma unroll
        for (int nt = 0; nt < 8; ++nt)
#pragma unroll
            for (int i = 0; i < 4; ++i) acc[mt][nt][i] = 0.f;

    const float *a, *b;
    int alda, bldb;

    // prologue: stages 0,1
#pragma unroll
    for (int s = 0; s < 2; ++s) {
        if (MODE == 1) chunk_src_1(s, brow, bcol, a, alda, b, bldb);
        else           chunk_src_2(s, brow, bcol, a, alda, b, bldb);
        issue_stage(a, alda, b, bldb, aoff[s], boff[s]);
        CP_COMMIT();
    }

    int buf = 0;
    for (int c = 0; c < C; ++c) {
        CP_WAIT1();            // stage c complete (only c+1 may remain in flight)
        __syncthreads();       // data visible; all warps done reading buf (c-1)%3
        if (c + 2 < C) {       // issue stage c+2 into buffer (c+2)%3
            if (MODE == 1) chunk_src_1(c + 2, brow, bcol, a, alda, b, bldb);
            else           chunk_src_2(c + 2, brow, bcol, a, alda, b, bldb);
            int s = (c + 2) % 3;
            issue_stage(a, alda, b, bldb, aoff[s], boff[s]);
        }
        CP_COMMIT();           // always commit to keep group accounting aligned
        compute_chunk(aoff[buf], boff[buf], acc, m0, n0, lane);
        buf = (buf + 1) % 3;
    }

    // Epilogue (m16n8 C layout: lane -> rows {r, r+8}, col pair 2*(lane&3))
    const int r = lane >> 2;
    const int cp = (lane & 3) * 2;
#pragma unroll
    for (int mt = 0; mt < 2; ++mt) {
        const int row0 = brow + m0 + mt * 16 + r;
        const int row1 = row0 + 8;
#pragma unroll
        for (int nt = 0; nt < 8; ++nt) {
            const int colbase = bcol + n0 + nt * 8;
            const int col = colbase + cp;
            if (MODE == 1) {
                const int g = colbase >> 5;
                const float s0 = g_ut_dt[row0 * U_DIM + g];
                const float s1 = g_ut_dt[row1 * U_DIM + g];
                float2 v0 = { tf32v(acc[mt][nt][0] * s0), tf32v(acc[mt][nt][1] * s0) };
                float2 v1 = { tf32v(acc[mt][nt][2] * s1), tf32v(acc[mt][nt][3] * s1) };
                *(float2*)&g_S[row0 * D_DIM + col] = v0;
                *(float2*)&g_S[row1 * D_DIM + col] = v1;
            } else {
                float2 v0 = { acc[mt][nt][0], acc[mt][nt][1] };
                float2 v1 = { acc[mt][nt][2], acc[mt][nt][3] };
                *(float2*)&outp[row0 * D_DIM + col] = v0;
                *(float2*)&outp[row1 * D_DIM + col] = v1;
            }
        }
    }
}

// ---------------------------------------------------------------------------
// yt = Z @ C^T + ut_dt @ D^T  (exact fp32)
// ---------------------------------------------------------------------------
__global__ void __launch_bounds__(128) yt_kernel(const float* __restrict__ Z,
                                                 const float* __restrict__ C,
                                                 const float* __restrict__ Dm,
                                                 float* __restrict__ yt)
{
    __shared__ float Cs[OBS_DIM][132];
    const int lane = threadIdx.x & 31;
    const int warp = threadIdx.x >> 5;
    const int b = blockIdx.x * 4 + warp;

    float acc[OBS_DIM];
    {
        float ud = g_ut_dt[b * U_DIM + lane];
#pragma unroll
        for (int o = 0; o < OBS_DIM; ++o) acc[o] = ud * Dm[o * U_DIM + lane];
    }
    for (int kt = 0; kt < D_DIM; kt += 128) {
        __syncthreads();
        for (int idx = threadIdx.x; idx < OBS_DIM * 128; idx += 128) {
            int o = idx >> 7, kk = idx & 127;
            Cs[o][kk] = C[o * D_DIM + kt + kk];
        }
        __syncthreads();
        float4 zv = *(const float4*)(Z + b * D_DIM + kt + lane * 4);
#pragma unroll
        for (int o = 0; o < OBS_DIM; ++o) {
            float4 cv = *(const float4*)&Cs[o][lane * 4];
            acc[o] += zv.x * cv.x + zv.y * cv.y + zv.z * cv.z + zv.w * cv.w;
        }
    }
#pragma unroll
    for (int o = 0; o < OBS_DIM; ++o) {
#pragma unroll
        for (int off = 16; off; off >>= 1)
            acc[o] += __shfl_xor_sync(0xffffffffu, acc[o], off);
    }
    if (lane == 0) {
#pragma unroll
        for (int o = 0; o < OBS_DIM; ++o) yt[b * OBS_DIM + o] = acc[o];
    }
}

// ---------------------------------------------------------------------------
// Launch
// ---------------------------------------------------------------------------
extern "C" void kernel_launch(void* const* d_in, const int* in_sizes, int n_in,
                              void* d_out, int out_size) {
    const float* z_dyn = (const float*)d_in[0];
    // d_in[1] = z_static (unused)
    const float* dt = (const float*)d_in[2];
    const float* ut = (const float*)d_in[3];
    const float* A = (const float*)d_in[4];
    const float* Bb = (const float*)d_in[5];
    const float* NP = (const float*)d_in[6];
    const float* NQ = (const float*)d_in[7];
    const float* C = (const float*)d_in[8];
    const float* Dm = (const float*)d_in[9];
    float* out = (float*)d_out;

    cudaFuncSetAttribute(gemm_mma<1>, cudaFuncAttributeMaxDynamicSharedMemorySize, SMEM_NEED);
    cudaFuncSetAttribute(gemm_mma<2>, cudaFuncAttributeMaxDynamicSharedMemorySize, SMEM_NEED);

    prep_fused<<<1024, 256>>>(z_dyn, A, Bb, NP, ut, dt);
    prep_wqT<<<dim3(D_DIM / 32, U_DIM), dim3(32, 32)>>>(NQ);

    dim3 grid(D_DIM / 256, B_DIM / 128);   // (4, 32) = 128 CTAs
    gemm_mma<1><<<grid, NTHREADS, SMEM_NEED>>>(out);
    gemm_mma<2><<<grid, NTHREADS, SMEM_NEED>>>(out);

    yt_kernel<<<B_DIM / 4, 128>>>(out, C, Dm, out + B_DIM * D_DIM);
}

// round 14
// speedup vs baseline: 1.2621x; 1.0895x over previous
#include <cuda_runtime.h>
#include <cstdint>

// Shapes (fixed): b=4096, d=1024, u=32, r=32, n_obs=25
#define B_DIM 4096
#define D_DIM 1024
#define U_DIM 32
#define OBS_DIM 25

// ---------------------------------------------------------------------------
// Device scratch (all GEMM operands pre-rounded to tf32)
// ---------------------------------------------------------------------------
__device__ float g_ut_dt[B_DIM * U_DIM];   // ut*dt, FULL fp32 (epilogue scales)
__device__ float g_utc[B_DIM * U_DIM];     // tf32-rounded ut*dt (GEMM operand)
__device__ float g_Zc[B_DIM * D_DIM];      // tf32-rounded z_dyn
__device__ float g_Ac[D_DIM * D_DIM];      // tf32-rounded A_bilinear       [N,K]
__device__ float g_Bc[D_DIM * U_DIM];      // tf32-rounded B_bilinear       [N,K]
__device__ float g_WqT[D_DIM * D_DIM];     // tf32  WqT[(m*32+r)][j] = N_Q[m,j,r]
__device__ float g_WpT[D_DIM * D_DIM];     // tf32  WpT[i][(m*32+r)] = N_P[m,i,r]
__device__ float g_S[B_DIM * D_DIM];       // tf32-rounded S[b, m*32+r]

// ---------------------------------------------------------------------------
// Helpers
// ---------------------------------------------------------------------------
__device__ __forceinline__ uint32_t f2tf32(float x) {
    uint32_t r;
    asm("cvt.rna.tf32.f32 %0, %1;" : "=r"(r) : "f"(x));
    return r;
}
__device__ __forceinline__ float tf32v(float x) { return __uint_as_float(f2tf32(x)); }
__device__ __forceinline__ uint32_t smem_u32(const void* p) {
    uint32_t a;
    asm("{ .reg .u64 t; cvta.to.shared.u64 t, %1; cvt.u32.u64 %0, t; }" : "=r"(a) : "l"(p));
    return a;
}
__device__ __forceinline__ void mma_tf32(float (&c)[4], const uint32_t (&a)[4],
                                         const uint32_t (&b)[2]) {
    asm volatile(
        "mma.sync.aligned.m16n8k8.row.col.f32.tf32.tf32.f32 "
        "{%0,%1,%2,%3}, {%4,%5,%6,%7}, {%8,%9}, {%0,%1,%2,%3};"
        : "+f"(c[0]), "+f"(c[1]), "+f"(c[2]), "+f"(c[3])
        : "r"(a[0]), "r"(a[1]), "r"(a[2]), "r"(a[3]), "r"(b[0]), "r"(b[1]));
}
__device__ __forceinline__ void ldsm4(uint32_t (&r)[4], uint32_t a) {
    asm volatile("ldmatrix.sync.aligned.m8n8.x4.shared.b16 {%0,%1,%2,%3}, [%4];"
                 : "=r"(r[0]), "=r"(r[1]), "=r"(r[2]), "=r"(r[3]) : "r"(a));
}
__device__ __forceinline__ void cp16(uint32_t dst, const void* src) {
    asm volatile("cp.async.cg.shared.global [%0], [%1], 16;" :: "r"(dst), "l"(src));
}
#define CP_COMMIT() asm volatile("cp.async.commit_group;" ::: "memory")
#define CP_WAIT1()  asm volatile("cp.async.wait_group 1;" ::: "memory")

// ---------------------------------------------------------------------------
// Prep: one fused grid-stride kernel (z, A, Wp, B, ut) + WqT smem transpose
// ---------------------------------------------------------------------------
__global__ void prep_fused(const float* __restrict__ z, const float* __restrict__ A,
                           const float* __restrict__ Bb, const float* __restrict__ NP,
                           const float* __restrict__ ut, const float* __restrict__ dt) {
    const int stride = gridDim.x * blockDim.x;
    const int tid = blockIdx.x * blockDim.x + threadIdx.x;
    const float dtv = dt[0];
    for (int i = tid; i < B_DIM * D_DIM; i += stride) g_Zc[i] = tf32v(z[i]);
    for (int i = tid; i < D_DIM * D_DIM; i += stride) g_Ac[i] = tf32v(A[i]);
    for (int i = tid; i < D_DIM * D_DIM; i += stride) {
        int ii = i >> 10, c = i & 1023, m = c >> 5, r = c & 31;
        g_WpT[i] = tf32v(NP[m * 32768 + ii * 32 + r]);
    }
    for (int i = tid; i < D_DIM * U_DIM; i += stride) g_Bc[i] = tf32v(Bb[i]);
    for (int i = tid; i < B_DIM * U_DIM; i += stride) {
        float v = ut[i] * dtv;
        g_ut_dt[i] = v;
        g_utc[i] = tf32v(v);
    }
}
__global__ void prep_wqT(const float* __restrict__ NQ) {
    __shared__ float t[32][33];
    int m = blockIdx.y;
    int j0 = blockIdx.x * 32;
    t[threadIdx.y][threadIdx.x] = NQ[m * 32768 + (j0 + threadIdx.y) * 32 + threadIdx.x];
    __syncthreads();
    g_WqT[(m * 32 + threadIdx.y) * D_DIM + j0 + threadIdx.x] = tf32v(t[threadIdx.x][threadIdx.y]);
}

// ---------------------------------------------------------------------------
// GEMM: CTA 128x256, BK=32, 256 threads = 8 warps (2m x 4n of 64x64 tiles).
// Smem row = 128B, 16B-unit swizzle (u ^ (row&7)).
// 3-stage cp.async pipeline: (A 16KB + B 32KB) x 3 = 144KB dynamic smem.
// Fragment DOUBLE-BUFFERING overlaps ldsm (k8+1) with mma (k8).
// ---------------------------------------------------------------------------
#define A_BYTES 16384
#define B_BYTES 32768
#define STAGE_BYTES (A_BYTES + B_BYTES)
#define SMEM_NEED (3 * STAGE_BYTES)
#define NTHREADS 256

__device__ __forceinline__ void chunk_src_1(int c, int brow, int bcol,
                                            const float*& a, int& alda,
                                            const float*& b, int& bldb) {
    a = g_Zc + brow * D_DIM + c * 32;   alda = D_DIM;
    b = g_WqT + bcol * D_DIM + c * 32;  bldb = D_DIM;
}
__device__ __forceinline__ void chunk_src_2(int c, int brow, int bcol,
                                            const float*& a, int& alda,
                                            const float*& b, int& bldb) {
    if (c < 32)      { a = g_Zc + brow * D_DIM + c * 32;         alda = D_DIM;
                       b = g_Ac + bcol * D_DIM + c * 32;         bldb = D_DIM; }
    else if (c < 64) { a = g_S + brow * D_DIM + (c - 32) * 32;   alda = D_DIM;
                       b = g_WpT + bcol * D_DIM + (c - 32) * 32; bldb = D_DIM; }
    else             { a = g_utc + brow * U_DIM;                 alda = U_DIM;
                       b = g_Bc + bcol * U_DIM;                  bldb = U_DIM; }
}

// One stage, 256 threads: A 1024 units (4/thread), B 2048 units (8/thread).
// Unit u of 16B: row = u>>3, q = u&7; consecutive t -> contiguous 128B reads.
__device__ __forceinline__ void issue_stage(const float* __restrict__ a, int alda,
                                            const float* __restrict__ b, int bldb,
                                            uint32_t abase, uint32_t bbase) {
    const int t = threadIdx.x;
#pragma unroll
    for (int i = 0; i < 4; ++i) {
        int u = t + i * NTHREADS;
        int row = u >> 3, q = u & 7;
        cp16(abase + row * 128 + ((q ^ (row & 7)) << 4), a + row * alda + q * 4);
    }
#pragma unroll
    for (int i = 0; i < 8; ++i) {
        int u = t + i * NTHREADS;
        int row = u >> 3, q = u & 7;
        cp16(bbase + row * 128 + ((q ^ (row & 7)) << 4), b + row * bldb + q * 4);
    }
}

// 64x64 warp tile, fragment double-buffered: per k8, 4 A-ldsm + 4 B-ldsm, 32 mma.
__device__ __forceinline__ void load_frags(uint32_t abase, uint32_t bbase,
                                           int m0, int n0, int lane, int c16b,
                                           uint32_t (&af)[4][4], uint32_t (&bf)[8][2]) {
    const int e3 = lane & 7;
    const int rA = e3 + ((lane >> 3) & 1) * 8;
    const int hA = lane >> 4;
    const int rB = e3 + ((lane >> 4) & 1) * 8;
    const int hB = (lane >> 3) & 1;
#pragma unroll
    for (int mt = 0; mt < 4; ++mt)
        ldsm4(af[mt], abase + (uint32_t)((m0 + mt * 16 + rA) * 128 +
                                         (((c16b + hA) ^ e3) << 4)));
#pragma unroll
    for (int p = 0; p < 4; ++p) {
        uint32_t tmp[4];
        ldsm4(tmp, bbase + (uint32_t)((n0 + p * 16 + rB) * 128 +
                                      (((c16b + hB) ^ e3) << 4)));
        bf[2 * p][0] = tmp[0]; bf[2 * p][1] = tmp[1];
        bf[2 * p + 1][0] = tmp[2]; bf[2 * p + 1][1] = tmp[3];
    }
}

__device__ __forceinline__ void compute_chunk(uint32_t abase, uint32_t bbase,
                                              float (&acc)[4][8][4],
                                              int m0, int n0, int lane) {
    uint32_t afr[2][4][4];
    uint32_t bfr[2][8][2];
    load_frags(abase, bbase, m0, n0, lane, 0, afr[0], bfr[0]);
#pragma unroll
    for (int kk = 0; kk < 4; ++kk) {
        const int cur = kk & 1, nxt = cur ^ 1;
        if (kk + 1 < 4)
            load_frags(abase, bbase, m0, n0, lane, 2 * (kk + 1), afr[nxt], bfr[nxt]);
#pragma unroll
        for (int mt = 0; mt < 4; ++mt)
#pragma unroll
            for (int nt = 0; nt < 8; ++nt)
                mma_tf32(acc[mt][nt], afr[cur][mt], bfr[cur][nt]);
    }
}

template <int MODE>   // 1: GEMM1 (C=32 -> g_S scaled+rounded); 2: GEMM2 (C=65 -> out)
__global__ void __launch_bounds__(NTHREADS, 1) gemm_mma(float* __restrict__ outp)
{
    extern __shared__ char dsm[];
    const uint32_t sb = smem_u32(dsm);
    uint32_t aoff[3], boff[3];
#pragma unroll
    for (int s = 0; s < 3; ++s) {
        aoff[s] = sb + s * STAGE_BYTES;
        boff[s] = sb + s * STAGE_BYTES + A_BYTES;
    }

    const int t = threadIdx.x;
    const int lane = t & 31;
    const int w = t >> 5;                 // 0..7
    const int m0 = (w >> 2) * 64;         // 2 m-groups of 64
    const int n0 = (w & 3) * 64;          // 4 n-groups of 64
    const int brow = blockIdx.y * 128;
    const int bcol = blockIdx.x * 256;
    const int C = (MODE == 1) ? 32 : 65;

    float acc[4][8][4];
#pragma unroll
    for (int mt = 0; mt < 4; ++mt)
#pragma unroll
        for (int nt = 0; nt < 8; ++nt)
#pragma unroll
            for (int i = 0; i < 4; ++i) acc[mt][nt][i] = 0.f;

    const float *a, *b;
    int alda, bldb;

    // prologue: stages 0,1
#pragma unroll
    for (int s = 0; s < 2; ++s) {
        if (MODE == 1) chunk_src_1(s, brow, bcol, a, alda, b, bldb);
        else           chunk_src_2(s, brow, bcol, a, alda, b, bldb);
        issue_stage(a, alda, b, bldb, aoff[s], boff[s]);
        CP_COMMIT();
    }

    int buf = 0;
    for (int c = 0; c < C; ++c) {
        CP_WAIT1();            // stage c complete (only c+1 may remain in flight)
        __syncthreads();       // data visible; all warps done reading buf (c-1)%3
        if (c + 2 < C) {       // issue stage c+2 into buffer (c+2)%3
            if (MODE == 1) chunk_src_1(c + 2, brow, bcol, a, alda, b, bldb);
            else           chunk_src_2(c + 2, brow, bcol, a, alda, b, bldb);
            int s = (c + 2) % 3;
            issue_stage(a, alda, b, bldb, aoff[s], boff[s]);
        }
        CP_COMMIT();           // always commit to keep group accounting aligned
        compute_chunk(aoff[buf], boff[buf], acc, m0, n0, lane);
        buf = (buf + 1) % 3;
    }

    // Epilogue (m16n8 C layout: lane -> rows {r, r+8}, col pair 2*(lane&3))
    const int r = lane >> 2;
    const int cp = (lane & 3) * 2;
#pragma unroll
    for (int mt = 0; mt < 4; ++mt) {
        const int row0 = brow + m0 + mt * 16 + r;
        const int row1 = row0 + 8;
#pragma unroll
        for (int nt = 0; nt < 8; ++nt) {
            const int colbase = bcol + n0 + nt * 8;
            const int col = colbase + cp;
            if (MODE == 1) {
                const int g = colbase >> 5;
                const float s0 = g_ut_dt[row0 * U_DIM + g];
                const float s1 = g_ut_dt[row1 * U_DIM + g];
                float2 v0 = { tf32v(acc[mt][nt][0] * s0), tf32v(acc[mt][nt][1] * s0) };
                float2 v1 = { tf32v(acc[mt][nt][2] * s1), tf32v(acc[mt][nt][3] * s1) };
                *(float2*)&g_S[row0 * D_DIM + col] = v0;
                *(float2*)&g_S[row1 * D_DIM + col] = v1;
            } else {
                float2 v0 = { acc[mt][nt][0], acc[mt][nt][1] };
                float2 v1 = { acc[mt][nt][2], acc[mt][nt][3] };
                *(float2*)&outp[row0 * D_DIM + col] = v0;
                *(float2*)&outp[row1 * D_DIM + col] = v1;
            }
        }
    }
}

// ---------------------------------------------------------------------------
// yt = Z @ C^T + ut_dt @ D^T  (exact fp32)
// ---------------------------------------------------------------------------
__global__ void __launch_bounds__(128) yt_kernel(const float* __restrict__ Z,
                                                 const float* __restrict__ C,
                                                 const float* __restrict__ Dm,
                                                 float* __restrict__ yt)
{
    __shared__ float Cs[OBS_DIM][132];
    const int lane = threadIdx.x & 31;
    const int warp = threadIdx.x >> 5;
    const int b = blockIdx.x * 4 + warp;

    float acc[OBS_DIM];
    {
        float ud = g_ut_dt[b * U_DIM + lane];
#pragma unroll
        for (int o = 0; o < OBS_DIM; ++o) acc[o] = ud * Dm[o * U_DIM + lane];
    }
    for (int kt = 0; kt < D_DIM; kt += 128) {
        __syncthreads();
        for (int idx = threadIdx.x; idx < OBS_DIM * 128; idx += 128) {
            int o = idx >> 7, kk = idx & 127;
            Cs[o][kk] = C[o * D_DIM + kt + kk];
        }
        __syncthreads();
        float4 zv = *(const float4*)(Z + b * D_DIM + kt + lane * 4);
#pragma unroll
        for (int o = 0; o < OBS_DIM; ++o) {
            float4 cv = *(const float4*)&Cs[o][lane * 4];
            acc[o] += zv.x * cv.x + zv.y * cv.y + zv.z * cv.z + zv.w * cv.w;
        }
    }
#pragma unroll
    for (int o = 0; o < OBS_DIM; ++o) {
#pragma unroll
        for (int off = 16; off; off >>= 1)
            acc[o] += __shfl_xor_sync(0xffffffffu, acc[o], off);
    }
    if (lane == 0) {
#pragma unroll
        for (int o = 0; o < OBS_DIM; ++o) yt[b * OBS_DIM + o] = acc[o];
    }
}

// ---------------------------------------------------------------------------
// Launch
// ---------------------------------------------------------------------------
extern "C" void kernel_launch(void* const* d_in, const int* in_sizes, int n_in,
                              void* d_out, int out_size) {
    const float* z_dyn = (const float*)d_in[0];
    // d_in[1] = z_static (unused)
    const float* dt = (const float*)d_in[2];
    const float* ut = (const float*)d_in[3];
    const float* A = (const float*)d_in[4];
    const float* Bb = (const float*)d_in[5];
    const float* NP = (const float*)d_in[6];
    const float* NQ = (const float*)d_in[7];
    const float* C = (const float*)d_in[8];
    const float* Dm = (const float*)d_in[9];
    float* out = (float*)d_out;

    cudaFuncSetAttribute(gemm_mma<1>, cudaFuncAttributeMaxDynamicSharedMemorySize, SMEM_NEED);
    cudaFuncSetAttribute(gemm_mma<2>, cudaFuncAttributeMaxDynamicSharedMemorySize, SMEM_NEED);

    prep_fused<<<1024, 256>>>(z_dyn, A, Bb, NP, ut, dt);
    prep_wqT<<<dim3(D_DIM / 32, U_DIM), dim3(32, 32)>>>(NQ);

    dim3 grid(D_DIM / 256, B_DIM / 128);   // (4, 32) = 128 CTAs
    gemm_mma<1><<<grid, NTHREADS, SMEM_NEED>>>(out);
    gemm_mma<2><<<grid, NTHREADS, SMEM_NEED>>>(out);

    yt_kernel<<<B_DIM / 4, 128>>>(out, C, Dm, out + B_DIM * D_DIM);
}

// round 16
// speedup vs baseline: 1.3485x; 1.0685x over previous
#include <cuda_runtime.h>
#include <cstdint>

// Shapes (fixed): b=4096, d=1024, u=32, r=32, n_obs=25
#define B_DIM 4096
#define D_DIM 1024
#define U_DIM 32
#define OBS_DIM 25

// ---------------------------------------------------------------------------
// Device scratch (all GEMM operands pre-rounded to tf32)
// ---------------------------------------------------------------------------
__device__ float g_ut_dt[B_DIM * U_DIM];   // ut*dt, FULL fp32 (epilogue scales)
__device__ float g_utc[B_DIM * U_DIM];     // tf32-rounded ut*dt (GEMM operand)
__device__ float g_Zc[B_DIM * D_DIM];      // tf32-rounded z_dyn
__device__ float g_Ac[D_DIM * D_DIM];      // tf32-rounded A_bilinear       [N,K]
__device__ float g_Bc[D_DIM * U_DIM];      // tf32-rounded B_bilinear       [N,K]
__device__ float g_WqT[D_DIM * D_DIM];     // tf32  WqT[(m*32+r)][j] = N_Q[m,j,r]
__device__ float g_WpT[D_DIM * D_DIM];     // tf32  WpT[i][(m*32+r)] = N_P[m,i,r]
__device__ float g_S[B_DIM * D_DIM];       // tf32-rounded S[b, m*32+r]

// ---------------------------------------------------------------------------
// Helpers
// ---------------------------------------------------------------------------
__device__ __forceinline__ uint32_t f2tf32(float x) {
    uint32_t r;
    asm("cvt.rna.tf32.f32 %0, %1;" : "=r"(r) : "f"(x));
    return r;
}
__device__ __forceinline__ float tf32v(float x) { return __uint_as_float(f2tf32(x)); }
__device__ __forceinline__ uint32_t smem_u32(const void* p) {
    uint32_t a;
    asm("{ .reg .u64 t; cvta.to.shared.u64 t, %1; cvt.u32.u64 %0, t; }" : "=r"(a) : "l"(p));
    return a;
}
__device__ __forceinline__ void mma_tf32(float (&c)[4], const uint32_t (&a)[4],
                                         const uint32_t (&b)[2]) {
    asm volatile(
        "mma.sync.aligned.m16n8k8.row.col.f32.tf32.tf32.f32 "
        "{%0,%1,%2,%3}, {%4,%5,%6,%7}, {%8,%9}, {%0,%1,%2,%3};"
        : "+f"(c[0]), "+f"(c[1]), "+f"(c[2]), "+f"(c[3])
        : "r"(a[0]), "r"(a[1]), "r"(a[2]), "r"(a[3]), "r"(b[0]), "r"(b[1]));
}
__device__ __forceinline__ void ldsm4(uint32_t (&r)[4], uint32_t a) {
    asm volatile("ldmatrix.sync.aligned.m8n8.x4.shared.b16 {%0,%1,%2,%3}, [%4];"
                 : "=r"(r[0]), "=r"(r[1]), "=r"(r[2]), "=r"(r[3]) : "r"(a));
}
__device__ __forceinline__ void cp16(uint32_t dst, const void* src) {
    asm volatile("cp.async.cg.shared.global [%0], [%1], 16;" :: "r"(dst), "l"(src));
}
#define CP_COMMIT() asm volatile("cp.async.commit_group;" ::: "memory")
#define CP_WAIT1()  asm volatile("cp.async.wait_group 1;" ::: "memory")

// ---------------------------------------------------------------------------
// Prep: one fused grid-stride kernel (z, A, Wp, B, ut) + WqT smem transpose
// ---------------------------------------------------------------------------
__global__ void prep_fused(const float* __restrict__ z, const float* __restrict__ A,
                           const float* __restrict__ Bb, const float* __restrict__ NP,
                           const float* __restrict__ ut, const float* __restrict__ dt) {
    const int stride = gridDim.x * blockDim.x;
    const int tid = blockIdx.x * blockDim.x + threadIdx.x;
    const float dtv = dt[0];
    for (int i = tid; i < B_DIM * D_DIM; i += stride) g_Zc[i] = tf32v(z[i]);
    for (int i = tid; i < D_DIM * D_DIM; i += stride) g_Ac[i] = tf32v(A[i]);
    for (int i = tid; i < D_DIM * D_DIM; i += stride) {
        int ii = i >> 10, c = i & 1023, m = c >> 5, r = c & 31;
        g_WpT[i] = tf32v(NP[m * 32768 + ii * 32 + r]);
    }
    for (int i = tid; i < D_DIM * U_DIM; i += stride) g_Bc[i] = tf32v(Bb[i]);
    for (int i = tid; i < B_DIM * U_DIM; i += stride) {
        float v = ut[i] * dtv;
        g_ut_dt[i] = v;
        g_utc[i] = tf32v(v);
    }
}
__global__ void prep_wqT(const float* __restrict__ NQ) {
    __shared__ float t[32][33];
    int m = blockIdx.y;
    int j0 = blockIdx.x * 32;
    t[threadIdx.y][threadIdx.x] = NQ[m * 32768 + (j0 + threadIdx.y) * 32 + threadIdx.x];
    __syncthreads();
    g_WqT[(m * 32 + threadIdx.y) * D_DIM + j0 + threadIdx.x] = tf32v(t[threadIdx.x][threadIdx.y]);
}

// ---------------------------------------------------------------------------
// GEMM: CTA 128x128, BK=32, 128 threads = 4 warps (2m x 2n of 64x64 tiles).
// TWO CTAs per SM (96KB smem each) so barriers/prologues of one CTA overlap
// with the other CTA's mma stream. Smem row = 128B, swizzle (u ^ (row&7)).
// 3-stage cp.async pipeline: (A 16KB + B 16KB) x 3 = 96KB dynamic smem.
// Fragment double-buffering overlaps ldsm (k8+1) with mma (k8).
// ---------------------------------------------------------------------------
#define A_BYTES 16384
#define B_BYTES 16384
#define STAGE_BYTES (A_BYTES + B_BYTES)
#define SMEM_NEED (3 * STAGE_BYTES)
#define NTHREADS 128

__device__ __forceinline__ void chunk_src_1(int c, int brow, int bcol,
                                            const float*& a, int& alda,
                                            const float*& b, int& bldb) {
    a = g_Zc + brow * D_DIM + c * 32;   alda = D_DIM;
    b = g_WqT + bcol * D_DIM + c * 32;  bldb = D_DIM;
}
__device__ __forceinline__ void chunk_src_2(int c, int brow, int bcol,
                                            const float*& a, int& alda,
                                            const float*& b, int& bldb) {
    if (c < 32)      { a = g_Zc + brow * D_DIM + c * 32;         alda = D_DIM;
                       b = g_Ac + bcol * D_DIM + c * 32;         bldb = D_DIM; }
    else if (c < 64) { a = g_S + brow * D_DIM + (c - 32) * 32;   alda = D_DIM;
                       b = g_WpT + bcol * D_DIM + (c - 32) * 32; bldb = D_DIM; }
    else             { a = g_utc + brow * U_DIM;                 alda = U_DIM;
                       b = g_Bc + bcol * U_DIM;                  bldb = U_DIM; }
}

// One stage, 128 threads: A 1024 units (8/thread), B 1024 units (8/thread).
// Unit u of 16B: row = u>>3, q = u&7; consecutive t -> contiguous 128B reads.
__device__ __forceinline__ void issue_stage(const float* __restrict__ a, int alda,
                                            const float* __restrict__ b, int bldb,
                                            uint32_t abase, uint32_t bbase) {
    const int t = threadIdx.x;
#pragma unroll
    for (int i = 0; i < 8; ++i) {
        int u = t + i * NTHREADS;
        int row = u >> 3, q = u & 7;
        cp16(abase + row * 128 + ((q ^ (row & 7)) << 4), a + row * alda + q * 4);
    }
#pragma unroll
    for (int i = 0; i < 8; ++i) {
        int u = t + i * NTHREADS;
        int row = u >> 3, q = u & 7;
        cp16(bbase + row * 128 + ((q ^ (row & 7)) << 4), b + row * bldb + q * 4);
    }
}

// 64x64 warp tile, fragment double-buffered: per k8, 4 A-ldsm + 4 B-ldsm, 32 mma.
__device__ __forceinline__ void load_frags(uint32_t abase, uint32_t bbase,
                                           int m0, int n0, int lane, int c16b,
                                           uint32_t (&af)[4][4], uint32_t (&bf)[8][2]) {
    const int e3 = lane & 7;
    const int rA = e3 + ((lane >> 3) & 1) * 8;
    const int hA = lane >> 4;
    const int rB = e3 + ((lane >> 4) & 1) * 8;
    const int hB = (lane >> 3) & 1;
#pragma unroll
    for (int mt = 0; mt < 4; ++mt)
        ldsm4(af[mt], abase + (uint32_t)((m0 + mt * 16 + rA) * 128 +
                                         (((c16b + hA) ^ e3) << 4)));
#pragma unroll
    for (int p = 0; p < 4; ++p) {
        uint32_t tmp[4];
        ldsm4(tmp, bbase + (uint32_t)((n0 + p * 16 + rB) * 128 +
                                      (((c16b + hB) ^ e3) << 4)));
        bf[2 * p][0] = tmp[0]; bf[2 * p][1] = tmp[1];
        bf[2 * p + 1][0] = tmp[2]; bf[2 * p + 1][1] = tmp[3];
    }
}

__device__ __forceinline__ void compute_chunk(uint32_t abase, uint32_t bbase,
                                              float (&acc)[4][8][4],
                                              int m0, int n0, int lane) {
    uint32_t afr[2][4][4];
    uint32_t bfr[2][8][2];
    load_frags(abase, bbase, m0, n0, lane, 0, afr[0], bfr[0]);
#pragma unroll
    for (int kk = 0; kk < 4; ++kk) {
        const int cur = kk & 1, nxt = cur ^ 1;
        if (kk + 1 < 4)
            load_frags(abase, bbase, m0, n0, lane, 2 * (kk + 1), afr[nxt], bfr[nxt]);
#pragma unroll
        for (int mt = 0; mt < 4; ++mt)
#pragma unroll
            for (int nt = 0; nt < 8; ++nt)
                mma_tf32(acc[mt][nt], afr[cur][mt], bfr[cur][nt]);
    }
}

template <int MODE>   // 1: GEMM1 (C=32 -> g_S scaled+rounded); 2: GEMM2 (C=65 -> out)
__global__ void __launch_bounds__(NTHREADS, 2) gemm_mma(float* __restrict__ outp)
{
    extern __shared__ char dsm[];
    const uint32_t sb = smem_u32(dsm);
    uint32_t aoff[3], boff[3];
#pragma unroll
    for (int s = 0; s < 3; ++s) {
        aoff[s] = sb + s * STAGE_BYTES;
        boff[s] = sb + s * STAGE_BYTES + A_BYTES;
    }

    const int t = threadIdx.x;
    const int lane = t & 31;
    const int w = t >> 5;                 // 0..3
    const int m0 = (w >> 1) * 64;         // 2 m-groups of 64
    const int n0 = (w & 1) * 64;          // 2 n-groups of 64
    const int brow = blockIdx.y * 128;
    const int bcol = blockIdx.x * 128;
    const int C = (MODE == 1) ? 32 : 65;

    float acc[4][8][4];
#pragma unroll
    for (int mt = 0; mt < 4; ++mt)
#pragma unroll
        for (int nt = 0; nt < 8; ++nt)
#pragma unroll
            for (int i = 0; i < 4; ++i) acc[mt][nt][i] = 0.f;

    const float *a, *b;
    int alda, bldb;

    // prologue: stages 0,1
#pragma unroll
    for (int s = 0; s < 2; ++s) {
        if (MODE == 1) chunk_src_1(s, brow, bcol, a, alda, b, bldb);
        else           chunk_src_2(s, brow, bcol, a, alda, b, bldb);
        issue_stage(a, alda, b, bldb, aoff[s], boff[s]);
        CP_COMMIT();
    }

    int buf = 0;
    for (int c = 0; c < C; ++c) {
        CP_WAIT1();            // stage c complete (only c+1 may remain in flight)
        __syncthreads();       // data visible; all warps done reading buf (c-1)%3
        if (c + 2 < C) {       // issue stage c+2 into buffer (c+2)%3
            if (MODE == 1) chunk_src_1(c + 2, brow, bcol, a, alda, b, bldb);
            else           chunk_src_2(c + 2, brow, bcol, a, alda, b, bldb);
            int s = (c + 2) % 3;
            issue_stage(a, alda, b, bldb, aoff[s], boff[s]);
        }
        CP_COMMIT();           // always commit to keep group accounting aligned
        compute_chunk(aoff[buf], boff[buf], acc, m0, n0, lane);
        buf = (buf + 1) % 3;
    }

    // Epilogue (m16n8 C layout: lane -> rows {r, r+8}, col pair 2*(lane&3))
    const int r = lane >> 2;
    const int cp = (lane & 3) * 2;
#pragma unroll
    for (int mt = 0; mt < 4; ++mt) {
        const int row0 = brow + m0 + mt * 16 + r;
        const int row1 = row0 + 8;
#pragma unroll
        for (int nt = 0; nt < 8; ++nt) {
            const int colbase = bcol + n0 + nt * 8;
            const int col = colbase + cp;
            if (MODE == 1) {
                const int g = colbase >> 5;
                const float s0 = g_ut_dt[row0 * U_DIM + g];
                const float s1 = g_ut_dt[row1 * U_DIM + g];
                float2 v0 = { tf32v(acc[mt][nt][0] * s0), tf32v(acc[mt][nt][1] * s0) };
                float2 v1 = { tf32v(acc[mt][nt][2] * s1), tf32v(acc[mt][nt][3] * s1) };
                *(float2*)&g_S[row0 * D_DIM + col] = v0;
                *(float2*)&g_S[row1 * D_DIM + col] = v1;
            } else {
                float2 v0 = { acc[mt][nt][0], acc[mt][nt][1] };
                float2 v1 = { acc[mt][nt][2], acc[mt][nt][3] };
                *(float2*)&outp[row0 * D_DIM + col] = v0;
                *(float2*)&outp[row1 * D_DIM + col] = v1;
            }
        }
    }
}

// ---------------------------------------------------------------------------
// yt = Z @ C^T + ut_dt @ D^T  (exact fp32)
// ---------------------------------------------------------------------------
__global__ void __launch_bounds__(128) yt_kernel(const float* __restrict__ Z,
                                                 const float* __restrict__ C,
                                                 const float* __restrict__ Dm,
                                                 float* __restrict__ yt)
{
    __shared__ float Cs[OBS_DIM][132];
    const int lane = threadIdx.x & 31;
    const int warp = threadIdx.x >> 5;
    const int b = blockIdx.x * 4 + warp;

    float acc[OBS_DIM];
    {
        float ud = g_ut_dt[b * U_DIM + lane];
#pragma unroll
        for (int o = 0; o < OBS_DIM; ++o) acc[o] = ud * Dm[o * U_DIM + lane];
    }
    for (int kt = 0; kt < D_DIM; kt += 128) {
        __syncthreads();
        for (int idx = threadIdx.x; idx < OBS_DIM * 128; idx += 128) {
            int o = idx >> 7, kk = idx & 127;
            Cs[o][kk] = C[o * D_DIM + kt + kk];
        }
        __syncthreads();
        float4 zv = *(const float4*)(Z + b * D_DIM + kt + lane * 4);
#pragma unroll
        for (int o = 0; o < OBS_DIM; ++o) {
            float4 cv = *(const float4*)&Cs[o][lane * 4];
            acc[o] += zv.x * cv.x + zv.y * cv.y + zv.z * cv.z + zv.w * cv.w;
        }
    }
#pragma unroll
    for (int o = 0; o < OBS_DIM; ++o) {
#pragma unroll
        for (int off = 16; off; off >>= 1)
            acc[o] += __shfl_xor_sync(0xffffffffu, acc[o], off);
    }
    if (lane == 0) {
#pragma unroll
        for (int o = 0; o < OBS_DIM; ++o) yt[b * OBS_DIM + o] = acc[o];
    }
}

// ---------------------------------------------------------------------------
// Launch
// ---------------------------------------------------------------------------
extern "C" void kernel_launch(void* const* d_in, const int* in_sizes, int n_in,
                              void* d_out, int out_size) {
    const float* z_dyn = (const float*)d_in[0];
    // d_in[1] = z_static (unused)
    const float* dt = (const float*)d_in[2];
    const float* ut = (const float*)d_in[3];
    const float* A = (const float*)d_in[4];
    const float* Bb = (const float*)d_in[5];
    const float* NP = (const float*)d_in[6];
    const float* NQ = (const float*)d_in[7];
    const float* C = (const float*)d_in[8];
    const float* Dm = (const float*)d_in[9];
    float* out = (float*)d_out;

    cudaFuncSetAttribute(gemm_mma<1>, cudaFuncAttributeMaxDynamicSharedMemorySize, SMEM_NEED);
    cudaFuncSetAttribute(gemm_mma<2>, cudaFuncAttributeMaxDynamicSharedMemorySize, SMEM_NEED);

    prep_fused<<<1024, 256>>>(z_dyn, A, Bb, NP, ut, dt);
    prep_wqT<<<dim3(D_DIM / 32, U_DIM), dim3(32, 32)>>>(NQ);

    dim3 grid(D_DIM / 128, B_DIM / 128);   // (8, 32) = 256 CTAs = 2/SM
    gemm_mma<1><<<grid, NTHREADS, SMEM_NEED>>>(out);
    gemm_mma<2><<<grid, NTHREADS, SMEM_NEED>>>(out);

    yt_kernel<<<B_DIM / 4, 128>>>(out, C, Dm, out + B_DIM * D_DIM);
}

// round 17
// speedup vs baseline: 1.4227x; 1.0550x over previous
#include <cuda_runtime.h>
#include <cstdint>

// Shapes (fixed): b=4096, d=1024, u=32, r=32, n_obs=25
#define B_DIM 4096
#define D_DIM 1024
#define U_DIM 32
#define OBS_DIM 25
#define OBS_PAD 32

// ---------------------------------------------------------------------------
// Device scratch (all GEMM operands pre-rounded to tf32)
// ---------------------------------------------------------------------------
__device__ float g_ut_dt[B_DIM * U_DIM];   // ut*dt, FULL fp32 (epilogue scales)
__device__ float g_utc[B_DIM * U_DIM];     // tf32-rounded ut*dt (GEMM operand)
__device__ float g_Zc[B_DIM * D_DIM];      // tf32-rounded z_dyn
__device__ float g_Ac[D_DIM * D_DIM];      // tf32-rounded A_bilinear       [N,K]
__device__ float g_Bc[D_DIM * U_DIM];      // tf32-rounded B_bilinear       [N,K]
__device__ float g_WqT[D_DIM * D_DIM];     // tf32  WqT[(m*32+r)][j] = N_Q[m,j,r]
__device__ float g_WpT[D_DIM * D_DIM];     // tf32  WpT[i][(m*32+r)] = N_P[m,i,r]
__device__ float g_S[B_DIM * D_DIM];       // tf32-rounded S[b, m*32+r]
__device__ float g_Cc[OBS_PAD * D_DIM];    // tf32-rounded C, rows 25..31 = 0
__device__ float g_YTs[4][B_DIM][OBS_PAD]; // yt partials per K-split (2 MB)

// ---------------------------------------------------------------------------
// Helpers
// ---------------------------------------------------------------------------
__device__ __forceinline__ uint32_t f2tf32(float x) {
    uint32_t r;
    asm("cvt.rna.tf32.f32 %0, %1;" : "=r"(r) : "f"(x));
    return r;
}
__device__ __forceinline__ float tf32v(float x) { return __uint_as_float(f2tf32(x)); }
__device__ __forceinline__ uint32_t smem_u32(const void* p) {
    uint32_t a;
    asm("{ .reg .u64 t; cvta.to.shared.u64 t, %1; cvt.u32.u64 %0, t; }" : "=r"(a) : "l"(p));
    return a;
}
__device__ __forceinline__ void mma_tf32(float (&c)[4], const uint32_t (&a)[4],
                                         const uint32_t (&b)[2]) {
    asm volatile(
        "mma.sync.aligned.m16n8k8.row.col.f32.tf32.tf32.f32 "
        "{%0,%1,%2,%3}, {%4,%5,%6,%7}, {%8,%9}, {%0,%1,%2,%3};"
        : "+f"(c[0]), "+f"(c[1]), "+f"(c[2]), "+f"(c[3])
        : "r"(a[0]), "r"(a[1]), "r"(a[2]), "r"(a[3]), "r"(b[0]), "r"(b[1]));
}
__device__ __forceinline__ void ldsm4(uint32_t (&r)[4], uint32_t a) {
    asm volatile("ldmatrix.sync.aligned.m8n8.x4.shared.b16 {%0,%1,%2,%3}, [%4];"
                 : "=r"(r[0]), "=r"(r[1]), "=r"(r[2]), "=r"(r[3]) : "r"(a));
}
__device__ __forceinline__ void cp16(uint32_t dst, const void* src) {
    asm volatile("cp.async.cg.shared.global [%0], [%1], 16;" :: "r"(dst), "l"(src));
}
#define CP_COMMIT() asm volatile("cp.async.commit_group;" ::: "memory")
#define CP_WAIT1()  asm volatile("cp.async.wait_group 1;" ::: "memory")

// ---------------------------------------------------------------------------
// Prep: one fused grid-stride kernel (z, A, Wp, B, ut, C) + WqT smem transpose
// ---------------------------------------------------------------------------
__global__ void prep_fused(const float* __restrict__ z, const float* __restrict__ A,
                           const float* __restrict__ Bb, const float* __restrict__ NP,
                           const float* __restrict__ ut, const float* __restrict__ dt,
                           const float* __restrict__ Cp) {
    const int stride = gridDim.x * blockDim.x;
    const int tid = blockIdx.x * blockDim.x + threadIdx.x;
    const float dtv = dt[0];
    for (int i = tid; i < B_DIM * D_DIM; i += stride) g_Zc[i] = tf32v(z[i]);
    for (int i = tid; i < D_DIM * D_DIM; i += stride) g_Ac[i] = tf32v(A[i]);
    for (int i = tid; i < D_DIM * D_DIM; i += stride) {
        int ii = i >> 10, c = i & 1023, m = c >> 5, r = c & 31;
        g_WpT[i] = tf32v(NP[m * 32768 + ii * 32 + r]);
    }
    for (int i = tid; i < D_DIM * U_DIM; i += stride) g_Bc[i] = tf32v(Bb[i]);
    for (int i = tid; i < B_DIM * U_DIM; i += stride) {
        float v = ut[i] * dtv;
        g_ut_dt[i] = v;
        g_utc[i] = tf32v(v);
    }
    for (int i = tid; i < OBS_PAD * D_DIM; i += stride) {
        int o = i >> 10;
        g_Cc[i] = (o < OBS_DIM) ? tf32v(Cp[i]) : 0.f;
    }
}
__global__ void prep_wqT(const float* __restrict__ NQ) {
    __shared__ float t[32][33];
    int m = blockIdx.y;
    int j0 = blockIdx.x * 32;
    t[threadIdx.y][threadIdx.x] = NQ[m * 32768 + (j0 + threadIdx.y) * 32 + threadIdx.x];
    __syncthreads();
    g_WqT[(m * 32 + threadIdx.y) * D_DIM + j0 + threadIdx.x] = tf32v(t[threadIdx.x][threadIdx.y]);
}

// ---------------------------------------------------------------------------
// GEMM: CTA 128x128, BK=32, 128 threads = 4 warps (2m x 2n of 64x64 tiles).
// TWO CTAs per SM (96KB smem each). Smem row = 128B, swizzle (u ^ (row&7)).
// 3-stage cp.async pipeline + fragment double-buffering.  (R16 best engine)
// ---------------------------------------------------------------------------
#define A_BYTES 16384
#define B_BYTES 16384
#define STAGE_BYTES (A_BYTES + B_BYTES)
#define SMEM_NEED (3 * STAGE_BYTES)
#define NTHREADS 128

__device__ __forceinline__ void chunk_src_1(int c, int brow, int bcol,
                                            const float*& a, int& alda,
                                            const float*& b, int& bldb) {
    a = g_Zc + brow * D_DIM + c * 32;   alda = D_DIM;
    b = g_WqT + bcol * D_DIM + c * 32;  bldb = D_DIM;
}
__device__ __forceinline__ void chunk_src_2(int c, int brow, int bcol,
                                            const float*& a, int& alda,
                                            const float*& b, int& bldb) {
    if (c < 32)      { a = g_Zc + brow * D_DIM + c * 32;         alda = D_DIM;
                       b = g_Ac + bcol * D_DIM + c * 32;         bldb = D_DIM; }
    else if (c < 64) { a = g_S + brow * D_DIM + (c - 32) * 32;   alda = D_DIM;
                       b = g_WpT + bcol * D_DIM + (c - 32) * 32; bldb = D_DIM; }
    else             { a = g_utc + brow * U_DIM;                 alda = U_DIM;
                       b = g_Bc + bcol * U_DIM;                  bldb = U_DIM; }
}

__device__ __forceinline__ void issue_stage(const float* __restrict__ a, int alda,
                                            const float* __restrict__ b, int bldb,
                                            uint32_t abase, uint32_t bbase) {
    const int t = threadIdx.x;
#pragma unroll
    for (int i = 0; i < 8; ++i) {
        int u = t + i * NTHREADS;
        int row = u >> 3, q = u & 7;
        cp16(abase + row * 128 + ((q ^ (row & 7)) << 4), a + row * alda + q * 4);
    }
#pragma unroll
    for (int i = 0; i < 8; ++i) {
        int u = t + i * NTHREADS;
        int row = u >> 3, q = u & 7;
        cp16(bbase + row * 128 + ((q ^ (row & 7)) << 4), b + row * bldb + q * 4);
    }
}

__device__ __forceinline__ void load_frags(uint32_t abase, uint32_t bbase,
                                           int m0, int n0, int lane, int c16b,
                                           uint32_t (&af)[4][4], uint32_t (&bf)[8][2]) {
    const int e3 = lane & 7;
    const int rA = e3 + ((lane >> 3) & 1) * 8;
    const int hA = lane >> 4;
    const int rB = e3 + ((lane >> 4) & 1) * 8;
    const int hB = (lane >> 3) & 1;
#pragma unroll
    for (int mt = 0; mt < 4; ++mt)
        ldsm4(af[mt], abase + (uint32_t)((m0 + mt * 16 + rA) * 128 +
                                         (((c16b + hA) ^ e3) << 4)));
#pragma unroll
    for (int p = 0; p < 4; ++p) {
        uint32_t tmp[4];
        ldsm4(tmp, bbase + (uint32_t)((n0 + p * 16 + rB) * 128 +
                                      (((c16b + hB) ^ e3) << 4)));
        bf[2 * p][0] = tmp[0]; bf[2 * p][1] = tmp[1];
        bf[2 * p + 1][0] = tmp[2]; bf[2 * p + 1][1] = tmp[3];
    }
}

__device__ __forceinline__ void compute_chunk(uint32_t abase, uint32_t bbase,
                                              float (&acc)[4][8][4],
                                              int m0, int n0, int lane) {
    uint32_t afr[2][4][4];
    uint32_t bfr[2][8][2];
    load_frags(abase, bbase, m0, n0, lane, 0, afr[0], bfr[0]);
#pragma unroll
    for (int kk = 0; kk < 4; ++kk) {
        const int cur = kk & 1, nxt = cur ^ 1;
        if (kk + 1 < 4)
            load_frags(abase, bbase, m0, n0, lane, 2 * (kk + 1), afr[nxt], bfr[nxt]);
#pragma unroll
        for (int mt = 0; mt < 4; ++mt)
#pragma unroll
            for (int nt = 0; nt < 8; ++nt)
                mma_tf32(acc[mt][nt], afr[cur][mt], bfr[cur][nt]);
    }
}

template <int MODE>   // 1: GEMM1 (C=32 -> g_S scaled+rounded); 2: GEMM2 (C=65 -> out)
__global__ void __launch_bounds__(NTHREADS, 2) gemm_mma(float* __restrict__ outp)
{
    extern __shared__ char dsm[];
    const uint32_t sb = smem_u32(dsm);
    uint32_t aoff[3], boff[3];
#pragma unroll
    for (int s = 0; s < 3; ++s) {
        aoff[s] = sb + s * STAGE_BYTES;
        boff[s] = sb + s * STAGE_BYTES + A_BYTES;
    }

    const int t = threadIdx.x;
    const int lane = t & 31;
    const int w = t >> 5;
    const int m0 = (w >> 1) * 64;
    const int n0 = (w & 1) * 64;
    const int brow = blockIdx.y * 128;
    const int bcol = blockIdx.x * 128;
    const int C = (MODE == 1) ? 32 : 65;

    float acc[4][8][4];
#pragma unroll
    for (int mt = 0; mt < 4; ++mt)
#pragma unroll
        for (int nt = 0; nt < 8; ++nt)
#pragma unroll
            for (int i = 0; i < 4; ++i) acc[mt][nt][i] = 0.f;

    const float *a, *b;
    int alda, bldb;

#pragma unroll
    for (int s = 0; s < 2; ++s) {
        if (MODE == 1) chunk_src_1(s, brow, bcol, a, alda, b, bldb);
        else           chunk_src_2(s, brow, bcol, a, alda, b, bldb);
        issue_stage(a, alda, b, bldb, aoff[s], boff[s]);
        CP_COMMIT();
    }

    int buf = 0;
    for (int c = 0; c < C; ++c) {
        CP_WAIT1();
        __syncthreads();
        if (c + 2 < C) {
            if (MODE == 1) chunk_src_1(c + 2, brow, bcol, a, alda, b, bldb);
            else           chunk_src_2(c + 2, brow, bcol, a, alda, b, bldb);
            int s = (c + 2) % 3;
            issue_stage(a, alda, b, bldb, aoff[s], boff[s]);
        }
        CP_COMMIT();
        compute_chunk(aoff[buf], boff[buf], acc, m0, n0, lane);
        buf = (buf + 1) % 3;
    }

    const int r = lane >> 2;
    const int cp = (lane & 3) * 2;
#pragma unroll
    for (int mt = 0; mt < 4; ++mt) {
        const int row0 = brow + m0 + mt * 16 + r;
        const int row1 = row0 + 8;
#pragma unroll
        for (int nt = 0; nt < 8; ++nt) {
            const int colbase = bcol + n0 + nt * 8;
            const int col = colbase + cp;
            if (MODE == 1) {
                const int g = colbase >> 5;
                const float s0 = g_ut_dt[row0 * U_DIM + g];
                const float s1 = g_ut_dt[row1 * U_DIM + g];
                float2 v0 = { tf32v(acc[mt][nt][0] * s0), tf32v(acc[mt][nt][1] * s0) };
                float2 v1 = { tf32v(acc[mt][nt][2] * s1), tf32v(acc[mt][nt][3] * s1) };
                *(float2*)&g_S[row0 * D_DIM + col] = v0;
                *(float2*)&g_S[row1 * D_DIM + col] = v1;
            } else {
                float2 v0 = { acc[mt][nt][0], acc[mt][nt][1] };
                float2 v1 = { acc[mt][nt][2], acc[mt][nt][3] };
                *(float2*)&outp[row0 * D_DIM + col] = v0;
                *(float2*)&outp[row1 * D_DIM + col] = v1;
            }
        }
    }
}

// ---------------------------------------------------------------------------
// yt via tensor cores: slab[ks][4096][32] = Z[:,ks*256:(ks+1)*256] @ CcT
// grid (4 ksplit, 32 row-blocks), 128 threads = 4 warps x 32 rows.
// ---------------------------------------------------------------------------
__global__ void __launch_bounds__(128) ytmma(const float* __restrict__ Z)
{
    __shared__ char zsm[16384];   // 128 rows x 128B (32 fp32), swizzled
    __shared__ char csm[4096];    // 32 rows  x 128B, swizzled
    const uint32_t zb = smem_u32(zsm);
    const uint32_t cb = smem_u32(csm);
    const int t = threadIdx.x;
    const int lane = t & 31;
    const int w = t >> 5;
    const int ks = blockIdx.x;
    const int mrow0 = blockIdx.y * 128;

    const int e3 = lane & 7;
    const int rA = e3 + ((lane >> 3) & 1) * 8;
    const int hA = lane >> 4;
    const int rB = e3 + ((lane >> 4) & 1) * 8;
    const int hB = (lane >> 3) & 1;

    float acc[2][4][4];
#pragma unroll
    for (int mt = 0; mt < 2; ++mt)
#pragma unroll
        for (int nt = 0; nt < 4; ++nt)
#pragma unroll
            for (int i = 0; i < 4; ++i) acc[mt][nt][i] = 0.f;

    for (int chunk = 0; chunk < 8; ++chunk) {
        const int kbase = ks * 256 + chunk * 32;
        __syncthreads();   // prior-iteration readers done before overwrite
        // stage Z tile (raw fp32; cvt post-ldsm)
#pragma unroll
        for (int i = 0; i < 8; ++i) {
            int u = t + i * 128;
            int row = u >> 3, q = u & 7;
            float4 v = *(const float4*)(Z + (mrow0 + row) * D_DIM + kbase + q * 4);
            *(float4*)(zsm + row * 128 + ((q ^ (row & 7)) << 4)) = v;
        }
        // stage Cc tile (pre-rounded tf32)
        {
            int u = t + (t < 128 ? 0 : 0);
            if (t < 256) {
                int uu = t;
                int row = uu >> 3, q = uu & 7;
                if (row < 32) {
                    float4 v = *(const float4*)(g_Cc + row * D_DIM + kbase + q * 4);
                    *(float4*)(csm + row * 128 + ((q ^ (row & 7)) << 4)) = v;
                }
            }
            // remaining 128 units by second pass
            int u2 = t + 128;
            int row = u2 >> 3, q = u2 & 7;
            if (row < 32) {
                float4 v = *(const float4*)(g_Cc + row * D_DIM + kbase + q * 4);
                *(float4*)(csm + row * 128 + ((q ^ (row & 7)) << 4)) = v;
            }
            (void)u;
        }
        __syncthreads();
#pragma unroll
        for (int k8 = 0; k8 < 4; ++k8) {
            const int c16b = 2 * k8;
            uint32_t af[2][4];
#pragma unroll
            for (int mt = 0; mt < 2; ++mt) {
                ldsm4(af[mt], zb + (uint32_t)((w * 32 + mt * 16 + rA) * 128 +
                                              (((c16b + hA) ^ e3) << 4)));
#pragma unroll
                for (int j = 0; j < 4; ++j)
                    af[mt][j] = f2tf32(__uint_as_float(af[mt][j]));
            }
            uint32_t bf[4][2];
#pragma unroll
            for (int p = 0; p < 2; ++p) {
                uint32_t tmp[4];
                ldsm4(tmp, cb + (uint32_t)((p * 16 + rB) * 128 +
                                           (((c16b + hB) ^ e3) << 4)));
                bf[2 * p][0] = tmp[0]; bf[2 * p][1] = tmp[1];
                bf[2 * p + 1][0] = tmp[2]; bf[2 * p + 1][1] = tmp[3];
            }
#pragma unroll
            for (int mt = 0; mt < 2; ++mt)
#pragma unroll
                for (int nt = 0; nt < 4; ++nt)
                    mma_tf32(acc[mt][nt], af[mt], bf[nt]);
        }
    }

    const int r = lane >> 2;
    const int cp = (lane & 3) * 2;
#pragma unroll
    for (int mt = 0; mt < 2; ++mt) {
        const int row0 = mrow0 + w * 32 + mt * 16 + r;
        const int row1 = row0 + 8;
#pragma unroll
        for (int nt = 0; nt < 4; ++nt) {
            const int col = nt * 8 + cp;
            g_YTs[ks][row0][col]     = acc[mt][nt][0];
            g_YTs[ks][row0][col + 1] = acc[mt][nt][1];
            g_YTs[ks][row1][col]     = acc[mt][nt][2];
            g_YTs[ks][row1][col + 1] = acc[mt][nt][3];
        }
    }
}

// yt[b,o] = dt * (ut[b,:]·Dm[o,:]) + sum_ks slab[ks][b][o]
__global__ void __launch_bounds__(256) yt_reduce(const float* __restrict__ ut,
                                                 const float* __restrict__ dt,
                                                 const float* __restrict__ Dm,
                                                 float* __restrict__ yt)
{
    int i = blockIdx.x * 256 + threadIdx.x;
    if (i >= B_DIM * OBS_DIM) return;
    int b = i / OBS_DIM, o = i - b * OBS_DIM;
    float s = 0.f;
#pragma unroll
    for (int u = 0; u < U_DIM; ++u)
        s += ut[b * U_DIM + u] * Dm[o * U_DIM + u];
    s *= dt[0];
#pragma unroll
    for (int ks = 0; ks < 4; ++ks)
        s += g_YTs[ks][b][o];
    yt[i] = s;
}

// ---------------------------------------------------------------------------
// Launch
// ---------------------------------------------------------------------------
extern "C" void kernel_launch(void* const* d_in, const int* in_sizes, int n_in,
                              void* d_out, int out_size) {
    const float* z_dyn = (const float*)d_in[0];
    // d_in[1] = z_static (unused)
    const float* dt = (const float*)d_in[2];
    const float* ut = (const float*)d_in[3];
    const float* A = (const float*)d_in[4];
    const float* Bb = (const float*)d_in[5];
    const float* NP = (const float*)d_in[6];
    const float* NQ = (const float*)d_in[7];
    const float* C = (const float*)d_in[8];
    const float* Dm = (const float*)d_in[9];
    float* out = (float*)d_out;

    cudaFuncSetAttribute(gemm_mma<1>, cudaFuncAttributeMaxDynamicSharedMemorySize, SMEM_NEED);
    cudaFuncSetAttribute(gemm_mma<2>, cudaFuncAttributeMaxDynamicSharedMemorySize, SMEM_NEED);

    prep_fused<<<1024, 256>>>(z_dyn, A, Bb, NP, ut, dt, C);
    prep_wqT<<<dim3(D_DIM / 32, U_DIM), dim3(32, 32)>>>(NQ);

    dim3 grid(D_DIM / 128, B_DIM / 128);   // (8, 32) = 256 CTAs = 2/SM
    gemm_mma<1><<<grid, NTHREADS, SMEM_NEED>>>(out);
    gemm_mma<2><<<grid, NTHREADS, SMEM_NEED>>>(out);

    ytmma<<<dim3(4, B_DIM / 128), 128>>>(out);
    yt_reduce<<<(B_DIM * OBS_DIM + 255) / 256, 256>>>(ut, dt, Dm, out + B_DIM * D_DIM);
}